// round 6
// baseline (speedup 1.0000x reference)
#include <cuda_runtime.h>

#define NN 20000
#define EE 40000
#define BB 32
#define SS 32
#define TT 64

#define CUT      0.06f      // |200*(lin-h)| >= 12 -> sigmoid treated as 0/1 (err <= 6.1e-6)
#define INV_STEP 15.5f      // (S-1)/(2*R)
// exp(-z) = exp2(288.539*(h+1) - s*18.61542),  z = 200*(lin[s]-h)
#define C_BASE   288.5390082f
#define C_STEP   18.61541988f

#define ESEG  2048
#define NCH_N 8
#define NCH_E 16
#define NODE_VB (BB * NCH_N)          // 256 virtual node blocks
#define EDGE_VB (BB * NCH_E)          // 512 virtual edge blocks
#define HIST_VB (NODE_VB + EDGE_VB)   // 768

#define R_OUT (BB * SS * TT)          // 65536
#define R_H   (NN * TT)               // 1280000
#define PREP_ITEMS (R_OUT + R_H + EE + NN)

// Scratch device globals. All state is either fully rewritten each call or
// self-resetting (cursors/tickets/barrier), so no init kernel is needed.
__device__ __align__(256) float g_h[NN * TT];     // node heights [n][t]
__device__ int2     g_epair[BB * ESEG];           // edges grouped by batch
__device__ unsigned g_ecur[BB];                   // relative cursors (0 at call start)
__device__ unsigned g_edone[BB];                  // 16-reader tickets (atomicInc wrap)
__device__ int      g_noff[BB + 1];               // node offsets (data-overwritten)
__device__ unsigned g_arrive;                     // monotonic grid-barrier counter

__global__ void __launch_bounds__(128)
fused_kernel(const float* __restrict__ x,
             const float* __restrict__ v,
             const int* __restrict__ ei,
             const int* __restrict__ batch,
             float* __restrict__ out) {
    __shared__ float hist[128 * 65];
    __shared__ int s_tot;

    const int tid = threadIdx.x;
    const int gstride = gridDim.x * 128;

    // ---------------- phase 1: zero out + heights + edge scatter + boundaries -----
    for (int i = blockIdx.x * 128 + tid; i < PREP_ITEMS; i += gstride) {
        if (i < R_OUT) {
            out[i] = 0.0f;
        } else if (i < R_OUT + R_H) {
            int k = i - R_OUT;
            int n = k >> 6, t = k & 63;
            const float* xp = x + n * 3;
            g_h[k] = fmaf(xp[0], v[t], fmaf(xp[1], v[TT + t], xp[2] * v[2 * TT + t]));
        } else if (i < R_OUT + R_H + EE) {
            int e = i - (R_OUT + R_H);
            int s = ei[e], d = ei[EE + e];
            int b = batch[s];
            unsigned pos = atomicAdd(&g_ecur[b], 1u);
            if (pos < ESEG) g_epair[b * ESEG + pos] = make_int2(s, d);
        } else {
            int n = i - (R_OUT + R_H + EE);
            int bn = batch[n];
            int bp = (n == 0) ? -1 : batch[n - 1];
            for (int b2 = bp + 1; b2 <= bn; ++b2) g_noff[b2] = n;
            if (n == NN - 1)
                for (int b2 = bn + 1; b2 <= BB; ++b2) g_noff[b2] = NN;  // sentinels
        }
    }

    // ---------------- device-wide barrier (self-resetting, monotonic) -------------
    __syncthreads();
    if (tid == 0) {
        __threadfence();                                  // release phase-1 writes
        unsigned ticket = atomicAdd(&g_arrive, 1u) + 1u;
        unsigned nb = gridDim.x;
        unsigned target = ((ticket + nb - 1u) / nb) * nb; // this call's release point
        while (atomicAdd(&g_arrive, 0u) < target) __nanosleep(64);
        __threadfence();                                  // acquire
    }
    __syncthreads();

    // ---------------- phase 2: private smem histograms over virtual blocks --------
    const int lane = tid & 31, wid = tid >> 5;
    const int c = tid >> 6;          // subchunk 0..1
    float* my = hist + tid * 65;

    for (int vb = blockIdx.x; vb < HIST_VB; vb += gridDim.x) {
        for (int i2 = tid; i2 < 128 * 65; i2 += 128) hist[i2] = 0.0f;

        bool is_node = vb < NODE_VB;
        int b, chunk, off, tot = 0, nch;
        float w;
        if (is_node) {
            b = vb >> 3; chunk = vb & 7;
            off = g_noff[b]; tot = g_noff[b + 1] - off; nch = NCH_N; w = 1.0f;
        } else {
            int eb = vb - NODE_VB;
            b = eb >> 4; chunk = eb & 15;
            off = b * ESEG; nch = NCH_E; w = -0.5f;
            if (tid == 0) {
                unsigned cnt = atomicAdd(&g_ecur[b], 0u);   // final count (post-barrier)
                s_tot = (cnt > (unsigned)ESEG) ? ESEG : (int)cnt;
                __threadfence();                             // read before ticket
                unsigned old = atomicInc(&g_edone[b], 15u);  // wraps 15 -> 0
                if (old == 15u) g_ecur[b] = 0u;              // 16th reader resets
            }
        }
        __syncthreads();
        if (!is_node) tot = s_tot;

        int per = (tot + nch - 1) / nch;
        int cs = off + chunk * per;
        int ce = min(off + tot, cs + per);
        int sub = (per + 1) >> 1;
        int ms = cs + c * sub;
        int me = min(ce, ms + sub);
        int t = tid & 63;

        #pragma unroll 2
        for (int i = ms; i < me; i++) {
            float h;
            if (is_node) {
                h = g_h[i * TT + t];                 // coalesced
            } else {
                int2 p = g_epair[i];                 // uniform broadcast
                h = fmaxf(g_h[p.x * TT + t], g_h[p.y * TT + t]);
            }
            float uh = fmaf(h, INV_STEP, (CUT + 1.0f) * INV_STEP);
            int s_hi = __float2int_ru(uh);
            if (s_hi < 0) s_hi = 0;
            if (s_hi < SS) my[s_hi] += w;            // step part
            int s_lo = __float2int_rd(uh - 2.0f * CUT * INV_STEP) + 1;
            if (s_lo < 0) s_lo = 0;
            int s_end = min(s_hi, SS);
            float base = fmaf(h, C_BASE, C_BASE);
            for (int s2 = s_lo; s2 < s_end; s2++) {  // exact band (~1.9 pts avg)
                float e2 = exp2f(fmaf((float)s2, -C_STEP, base));
                float sig = __fdividef(1.0f, 1.0f + e2);
                my[32 + s2] += w * sig;
            }
        }
        __syncthreads();

        // merge subchunk 1 into subchunk 0
        for (int k = tid; k < 64 * 64; k += 128) {
            int t2 = k >> 6, bin = k & 63;
            hist[t2 * 65 + bin] += hist[(64 + t2) * 65 + bin];
        }
        __syncthreads();

        // inclusive prefix over s (lanes = s, stride-65 -> conflict-free)
        for (int j = 0; j < 16; j++) {
            int t2 = wid * 16 + j;
            float cv = hist[t2 * 65 + lane];
            for (int o = 1; o < 32; o <<= 1) {
                float a = __shfl_up_sync(0xffffffffu, cv, o);
                if (lane >= o) cv += a;
            }
            hist[t2 * 65 + lane] = cv + hist[t2 * 65 + 32 + lane];
        }
        __syncthreads();

        // coalesced flush into out[b][s][t], lanes = t
        int t0 = (wid & 1) * 32;
        for (int s2 = wid >> 1; s2 < SS; s2 += 2) {
            float val = hist[(t0 + lane) * 65 + s2];
            atomicAdd(&out[(b * SS + s2) * TT + t0 + lane], val);
        }
        __syncthreads();   // protect hist reuse in next vb
    }
}

extern "C" void kernel_launch(void* const* d_in, const int* in_sizes, int n_in,
                              void* d_out, int out_size) {
    const float* x     = (const float*)d_in[0];
    const float* v     = (const float*)d_in[1];
    const int*   ei    = (const int*)d_in[3];
    const int*   batch = (const int*)d_in[4];
    float* out = (float*)d_out;

    // Guaranteed-resident grid: query occupancy (pure host query, capture-safe).
    int nb_sm = 0, nsm = 0, dev = 0;
    cudaOccupancyMaxActiveBlocksPerMultiprocessor(&nb_sm, fused_kernel, 128, 0);
    cudaGetDevice(&dev);
    cudaDeviceGetAttribute(&nsm, cudaDevAttrMultiProcessorCount, dev);
    if (nb_sm < 1) nb_sm = 1;
    if (nsm < 1) nsm = 1;
    long long nb = (long long)nb_sm * nsm;
    if (nb > HIST_VB) nb = HIST_VB;

    fused_kernel<<<(int)nb, 128>>>(x, v, ei, batch, out);
}